// round 5
// baseline (speedup 1.0000x reference)
#include <cuda_runtime.h>
#include <math.h>

// NPSLoss: mean over pixels of sqrt(min_k ||p - c_k||^2), 20-color fixed codebook.
// d2_k = |p|^2 + s_k,  s_k = |c_k|^2 - 2 p.c_k.  All non-black s_k are DECREASING
// affine functions of one of:
//   vmax = max(r,g,b)          (9 single-channel colors -> 3 lines)
//   smax = rgb - min(r,g,b)    (6 two-channel colors    -> 2 lines)
//   rgb  = r+g+b               (4 gray colors           -> 4 lines)
// Black (0,0,0): s = 0 -> d2 candidate = |p|^2.

#define HW_SHIFT 18            // 512*512
#define HW (1 << HW_SHIFT)
#define NBLOCKS 1184           // 148 SMs * 8 queued CTAs (6 resident, 2-wave steal)

__device__ float    g_partials[NBLOCKS];
__device__ unsigned g_count;   // self-resetting ticket (0 after every launch)

struct f8 { float v[8]; };

__device__ __forceinline__ f8 ldg_el8(const float* p) {
    unsigned a0, a1, a2, a3, a4, a5, a6, a7;
    asm("ld.global.nc.L2::evict_last.v8.b32 {%0,%1,%2,%3,%4,%5,%6,%7}, [%8];"
        : "=r"(a0), "=r"(a1), "=r"(a2), "=r"(a3),
          "=r"(a4), "=r"(a5), "=r"(a6), "=r"(a7)
        : "l"(p));
    f8 o;
    o.v[0] = __uint_as_float(a0); o.v[1] = __uint_as_float(a1);
    o.v[2] = __uint_as_float(a2); o.v[3] = __uint_as_float(a3);
    o.v[4] = __uint_as_float(a4); o.v[5] = __uint_as_float(a5);
    o.v[6] = __uint_as_float(a6); o.v[7] = __uint_as_float(a7);
    return o;
}

__device__ __forceinline__ float pix_dist(float r, float g, float b) {
    float rgb  = (r + g) + b;
    float vmax = fmaxf(fmaxf(r, g), b);
    float vmin = fminf(fminf(r, g), b);
    float smax = rgb - vmin;                       // max of the pair sums
    float pp   = fmaf(r, r, fmaf(g, g, b * b));

    // single-channel colors c in {0.5, 0.75, 1}, evaluated at vmax
    float m1 = fminf(0.25f - vmax, fmaf(-1.5f, vmax, 0.5625f));
    m1 = fminf(m1, fmaf(-2.0f, vmax, 1.0f));
    // pair colors c in {0.5, 1}, evaluated at smax
    float m2 = fminf(0.5f - smax, fmaf(-2.0f, smax, 2.0f));
    // grays c in {0.25, 0.5, 0.75, 1}, evaluated at rgb
    float m3 = fminf(fmaf(-0.5f, rgb, 0.1875f), 0.75f - rgb);
    m3 = fminf(m3, fminf(fmaf(-1.5f, rgb, 1.6875f), fmaf(-2.0f, rgb, 3.0f)));

    float m  = fminf(fminf(m1, m2), m3);
    float d2 = fminf(pp + m, pp);                  // black color: s = 0
    float y;
    asm("sqrt.approx.f32 %0, %1;" : "=f"(y) : "f"(fabsf(d2)));
    return y;
}

__global__ void __launch_bounds__(256) nps_loss_kernel(
    const float* __restrict__ x, float* __restrict__ out,
    int n_groups, float inv_n)
{
    float acc0 = 0.0f, acc1 = 0.0f;
    const int stride = gridDim.x * blockDim.x;
    for (int gi = blockIdx.x * blockDim.x + threadIdx.x; gi < n_groups; gi += stride) {
        int p   = gi << 3;                 // 8 pixels per group
        int img = p >> HW_SHIFT;
        int off = p & (HW - 1);
        const float* base = x + (size_t)img * (3 * HW) + off;
        // 3 front-batched 32B loads
        f8 r = ldg_el8(base);
        f8 g = ldg_el8(base + HW);
        f8 b = ldg_el8(base + 2 * HW);

        acc0 += pix_dist(r.v[0], g.v[0], b.v[0]);
        acc1 += pix_dist(r.v[1], g.v[1], b.v[1]);
        acc0 += pix_dist(r.v[2], g.v[2], b.v[2]);
        acc1 += pix_dist(r.v[3], g.v[3], b.v[3]);
        acc0 += pix_dist(r.v[4], g.v[4], b.v[4]);
        acc1 += pix_dist(r.v[5], g.v[5], b.v[5]);
        acc0 += pix_dist(r.v[6], g.v[6], b.v[6]);
        acc1 += pix_dist(r.v[7], g.v[7], b.v[7]);
    }
    float acc = acc0 + acc1;

    // warp reduction
    #pragma unroll
    for (int sh = 16; sh > 0; sh >>= 1)
        acc += __shfl_xor_sync(0xFFFFFFFFu, acc, sh);

    __shared__ float warp_sums[8];
    __shared__ bool  is_last;
    int lane = threadIdx.x & 31;
    int wid  = threadIdx.x >> 5;
    if (lane == 0) warp_sums[wid] = acc;
    __syncthreads();

    if (threadIdx.x == 0) {
        float v = warp_sums[0];
        #pragma unroll
        for (int w = 1; w < 8; w++) v += warp_sums[w];
        g_partials[blockIdx.x] = v;
        __threadfence();
        unsigned t = atomicAdd(&g_count, 1u);
        is_last = (t == gridDim.x - 1);
    }
    __syncthreads();

    // Last block deterministically reduces all partials and writes the result.
    if (is_last) {
        int nb = gridDim.x;
        float v = 0.0f;
        for (int i = threadIdx.x; i < nb; i += blockDim.x)
            v += g_partials[i];
        #pragma unroll
        for (int sh = 16; sh > 0; sh >>= 1)
            v += __shfl_xor_sync(0xFFFFFFFFu, v, sh);
        if (lane == 0) warp_sums[wid] = v;
        __syncthreads();
        if (threadIdx.x == 0) {
            float tot = warp_sums[0];
            #pragma unroll
            for (int w = 1; w < 8; w++) tot += warp_sums[w];
            out[0]  = tot * inv_n;
            g_count = 0;                 // reset for next graph replay
        }
    }
}

extern "C" void kernel_launch(void* const* d_in, const int* in_sizes, int n_in,
                              void* d_out, int out_size)
{
    const float* x = (const float*)d_in[0];
    float* out = (float*)d_out;

    int n_elems  = in_sizes[0];          // B*3*H*W
    int n_pixels = n_elems / 3;          // 8388608
    int n_groups = n_pixels >> 3;        // 8 pixels per group
    float inv_n  = 1.0f / (float)n_pixels;

    nps_loss_kernel<<<NBLOCKS, 256>>>(x, out, n_groups, inv_n);
}

// round 6
// speedup vs baseline: 1.1385x; 1.1385x over previous
#include <cuda_runtime.h>
#include <math.h>

// NPSLoss: mean over pixels of sqrt(min_k ||p - c_k||^2), 20-color fixed codebook.
// d2_k = |p|^2 + s_k,  s_k = |c_k|^2 - 2 p.c_k.  All non-black s_k are DECREASING
// affine functions of one of:
//   vmax = max(r,g,b)          (9 single-channel colors -> 3 lines)
//   smax = rgb - min(r,g,b)    (6 two-channel colors    -> 2 lines)
//   rgb  = r+g+b               (4 gray colors           -> 4 lines)
// Black (0,0,0): s = 0 -> d2 candidate = |p|^2.
//
// R6 = exact restore of the R3 champion (17.15us): grid-stride, 1184 blocks
// (148 SMs x 8 CTAs exactly -> per-SM work equal), single accumulator chain,
// separate zero-kernel + atomicAdd epilogue, evict_last 32B loads.

#define HW_SHIFT 18            // 512*512
#define HW (1 << HW_SHIFT)

struct f8 { float v[8]; };

__device__ __forceinline__ f8 ldg_el8(const float* p) {
    unsigned a0, a1, a2, a3, a4, a5, a6, a7;
    asm("ld.global.nc.L2::evict_last.v8.b32 {%0,%1,%2,%3,%4,%5,%6,%7}, [%8];"
        : "=r"(a0), "=r"(a1), "=r"(a2), "=r"(a3),
          "=r"(a4), "=r"(a5), "=r"(a6), "=r"(a7)
        : "l"(p));
    f8 o;
    o.v[0] = __uint_as_float(a0); o.v[1] = __uint_as_float(a1);
    o.v[2] = __uint_as_float(a2); o.v[3] = __uint_as_float(a3);
    o.v[4] = __uint_as_float(a4); o.v[5] = __uint_as_float(a5);
    o.v[6] = __uint_as_float(a6); o.v[7] = __uint_as_float(a7);
    return o;
}

__device__ __forceinline__ float pix_dist(float r, float g, float b) {
    float rgb  = (r + g) + b;
    float vmax = fmaxf(fmaxf(r, g), b);
    float vmin = fminf(fminf(r, g), b);
    float smax = rgb - vmin;                       // max of the pair sums
    float pp   = fmaf(r, r, fmaf(g, g, b * b));

    // single-channel colors c in {0.5, 0.75, 1}, evaluated at vmax
    float m1 = fminf(0.25f - vmax, fmaf(-1.5f, vmax, 0.5625f));
    m1 = fminf(m1, fmaf(-2.0f, vmax, 1.0f));
    // pair colors c in {0.5, 1}, evaluated at smax
    float m2 = fminf(0.5f - smax, fmaf(-2.0f, smax, 2.0f));
    // grays c in {0.25, 0.5, 0.75, 1}, evaluated at rgb
    float m3 = fminf(fmaf(-0.5f, rgb, 0.1875f), 0.75f - rgb);
    m3 = fminf(m3, fminf(fmaf(-1.5f, rgb, 1.6875f), fmaf(-2.0f, rgb, 3.0f)));

    float m  = fminf(fminf(m1, m2), m3);
    float d2 = fminf(pp + m, pp);                  // black color: s = 0
    float y;
    asm("sqrt.approx.f32 %0, %1;" : "=f"(y) : "f"(fabsf(d2)));
    return y;
}

__global__ void nps_zero_kernel(float* out) {
    if (threadIdx.x == 0 && blockIdx.x == 0) out[0] = 0.0f;
}

__global__ void __launch_bounds__(256) nps_loss_kernel(
    const float* __restrict__ x, float* __restrict__ out,
    int n_pairs, float inv_n)
{
    float acc = 0.0f;
    const int stride = gridDim.x * blockDim.x;
    for (int pi = blockIdx.x * blockDim.x + threadIdx.x; pi < n_pairs; pi += stride) {
        int p   = pi << 3;                 // 8 pixels per iteration
        int img = p >> HW_SHIFT;
        int off = p & (HW - 1);
        const float* base = x + (size_t)img * (3 * HW) + off;
        // 3 front-batched 32B loads -> high MLP, low issue pressure
        f8 r = ldg_el8(base);
        f8 g = ldg_el8(base + HW);
        f8 b = ldg_el8(base + 2 * HW);

        #pragma unroll
        for (int i = 0; i < 8; i++)
            acc += pix_dist(r.v[i], g.v[i], b.v[i]);
    }

    // warp reduction
    #pragma unroll
    for (int sh = 16; sh > 0; sh >>= 1)
        acc += __shfl_xor_sync(0xFFFFFFFFu, acc, sh);

    __shared__ float warp_sums[8];
    int lane = threadIdx.x & 31;
    int wid  = threadIdx.x >> 5;
    if (lane == 0) warp_sums[wid] = acc;
    __syncthreads();

    if (wid == 0) {
        float v = (lane < (blockDim.x >> 5)) ? warp_sums[lane] : 0.0f;
        #pragma unroll
        for (int sh = 4; sh > 0; sh >>= 1)
            v += __shfl_xor_sync(0xFFFFFFFFu, v, sh);
        if (lane == 0) atomicAdd(out, v * inv_n);
    }
}

extern "C" void kernel_launch(void* const* d_in, const int* in_sizes, int n_in,
                              void* d_out, int out_size)
{
    const float* x = (const float*)d_in[0];
    float* out = (float*)d_out;

    int n_elems  = in_sizes[0];          // B*3*H*W
    int n_pixels = n_elems / 3;          // 8388608
    int n_pairs  = n_pixels >> 3;        // 8 pixels per iteration
    float inv_n  = 1.0f / (float)n_pixels;

    nps_zero_kernel<<<1, 32>>>(out);

    const int threads = 256;
    int blocks = (n_pairs + threads - 1) / threads;
    const int max_blocks = 148 * 8;      // 148 SMs x 8 CTAs exactly
    if (blocks > max_blocks) blocks = max_blocks;
    nps_loss_kernel<<<blocks, threads>>>(x, out, n_pairs, inv_n);
}